// round 13
// baseline (speedup 1.0000x reference)
#include <cuda_runtime.h>
#include <cstdint>

// Graph unpooling: out[dst] += edge_attr * x[src]
//   x [50000,128] f32, src/dst [E=800000] i32, edge_attr [E] f32, out [200000,128] f32
// Fixed-capacity binning (8 slots/node, ~98% of Poisson(4) fan-in), overflow
// list. Self-cleaning state: gather re-zeroes counts, spill's last block
// re-zeroes the overflow counter -> no reset kernel needed.

#define MAXN   200704
#define MAXE   800000
#define CAP    8
#define SPILL_BLOCKS 128

__device__ int  g_count[MAXN];         // per-node edge count (zero at load; self-cleaned)
__device__ int2 g_slots[MAXN * CAP];   // {src, bitcast(weight)} per slot
__device__ int  g_ovf_n;               // overflow counter (self-cleaned)
__device__ int  g_done;                // spill done-ticket (self-cleaned)
__device__ int4 g_ovf[MAXE];           // overflow: {src, dst, w_bits, pad}

// Fused hist+fill: bin each edge into its node's slot array (or overflow).
__global__ void k_bin(const int* __restrict__ src, const int* __restrict__ dst,
                      const float* __restrict__ attr, int E) {
    int e = blockIdx.x * blockDim.x + threadIdx.x;
    if (e >= E) return;
    int d = __ldg(&dst[e]);
    int s = __ldg(&src[e]);
    int w = __float_as_int(__ldg(&attr[e]));
    int r = atomicAdd(&g_count[d], 1);
    if (r < CAP) {
        g_slots[d * CAP + r] = make_int2(s, w);
    } else {
        int p = atomicAdd(&g_ovf_n, 1);
        g_ovf[p] = make_int4(s, d, w, 0);
    }
}

// One warp per fine node: predicated 4-burst x2 over the 8 fixed slots,
// register accumulate, single streaming store (keeps x resident in L2).
// Lane 0 re-zeroes this node's count for the next call.
__global__ void __launch_bounds__(256)
k_gather(const float4* __restrict__ x4, float4* __restrict__ out4, int n) {
    int gtid = blockIdx.x * blockDim.x + threadIdx.x;
    int node = gtid >> 5;
    int lane = gtid & 31;
    if (node >= n) return;

    int cnt = __ldg(&g_count[node]);
    if (lane == 0) g_count[node] = 0;          // self-clean for next call
    if (cnt > CAP) cnt = CAP;
    int beg = node * CAP;

    const float4 fz = make_float4(0.f, 0.f, 0.f, 0.f);
    float4 a0 = fz, a1 = fz;

    // burst 1: slots 0..3 (covers 63% of nodes entirely)
    int2 e0 = make_int2(0, 0), e1 = e0, e2 = e0, e3 = e0;
    if (cnt > 0) e0 = __ldg(&g_slots[beg]);
    if (cnt > 1) e1 = __ldg(&g_slots[beg + 1]);
    if (cnt > 2) e2 = __ldg(&g_slots[beg + 2]);
    if (cnt > 3) e3 = __ldg(&g_slots[beg + 3]);
    float4 v0 = fz, v1 = fz, v2 = fz, v3 = fz;
    if (cnt > 0) v0 = __ldg(&x4[(size_t)e0.x * 32 + lane]);
    if (cnt > 1) v1 = __ldg(&x4[(size_t)e1.x * 32 + lane]);
    if (cnt > 2) v2 = __ldg(&x4[(size_t)e2.x * 32 + lane]);
    if (cnt > 3) v3 = __ldg(&x4[(size_t)e3.x * 32 + lane]);
    {
        float w0 = __int_as_float(e0.y), w1 = __int_as_float(e1.y);
        float w2 = __int_as_float(e2.y), w3 = __int_as_float(e3.y);
        a0.x += w0 * v0.x; a0.y += w0 * v0.y; a0.z += w0 * v0.z; a0.w += w0 * v0.w;
        a1.x += w1 * v1.x; a1.y += w1 * v1.y; a1.z += w1 * v1.z; a1.w += w1 * v1.w;
        a0.x += w2 * v2.x; a0.y += w2 * v2.y; a0.z += w2 * v2.z; a0.w += w2 * v2.w;
        a1.x += w3 * v3.x; a1.y += w3 * v3.y; a1.z += w3 * v3.z; a1.w += w3 * v3.w;
    }

    // burst 2: slots 4..7 (predicated; rare)
    if (cnt > 4) {
        int2 f0 = __ldg(&g_slots[beg + 4]);
        int2 f1 = make_int2(0, 0), f2 = f1, f3 = f1;
        if (cnt > 5) f1 = __ldg(&g_slots[beg + 5]);
        if (cnt > 6) f2 = __ldg(&g_slots[beg + 6]);
        if (cnt > 7) f3 = __ldg(&g_slots[beg + 7]);
        float4 u0 = __ldg(&x4[(size_t)f0.x * 32 + lane]);
        float4 u1 = fz, u2 = fz, u3 = fz;
        if (cnt > 5) u1 = __ldg(&x4[(size_t)f1.x * 32 + lane]);
        if (cnt > 6) u2 = __ldg(&x4[(size_t)f2.x * 32 + lane]);
        if (cnt > 7) u3 = __ldg(&x4[(size_t)f3.x * 32 + lane]);
        float w0 = __int_as_float(f0.y), w1 = __int_as_float(f1.y);
        float w2 = __int_as_float(f2.y), w3 = __int_as_float(f3.y);
        a0.x += w0 * u0.x; a0.y += w0 * u0.y; a0.z += w0 * u0.z; a0.w += w0 * u0.w;
        a1.x += w1 * u1.x; a1.y += w1 * u1.y; a1.z += w1 * u1.z; a1.w += w1 * u1.w;
        a0.x += w2 * u2.x; a0.y += w2 * u2.y; a0.z += w2 * u2.z; a0.w += w2 * u2.w;
        a1.x += w3 * u3.x; a1.y += w3 * u3.y; a1.z += w3 * u3.z; a1.w += w3 * u3.w;
    }

    a0.x += a1.x; a0.y += a1.y; a0.z += a1.z; a0.w += a1.w;
    __stcs(&out4[(size_t)node * 32 + lane], a0);
}

// Overflow edges: warp strided over entries, red.add.v4 into out.
// Last-finishing block (done-ticket) re-zeroes g_ovf_n and the ticket.
__global__ void __launch_bounds__(256)
k_spill(const float4* __restrict__ x4, float* __restrict__ out, int total_warps) {
    int gtid = blockIdx.x * blockDim.x + threadIdx.x;
    int warp = gtid >> 5;
    int lane = gtid & 31;
    int m = g_ovf_n;                // every block reads before any zeroing
    for (int i = warp; i < m; i += total_warps) {
        int4 e = g_ovf[i];
        float w = __int_as_float(e.z);
        float4 v = __ldg(&x4[(size_t)e.x * 32 + lane]);
        v.x *= w; v.y *= w; v.z *= w; v.w *= w;
        float* p = out + (size_t)e.y * 128 + (lane << 2);
        asm volatile("red.global.add.v4.f32 [%0], {%1, %2, %3, %4};"
                     :: "l"(p), "f"(v.x), "f"(v.y), "f"(v.z), "f"(v.w)
                     : "memory");
    }
    __syncthreads();
    if (threadIdx.x == 0) {
        int t = atomicAdd(&g_done, 1);
        if (t == gridDim.x - 1) {   // last block to finish: self-clean
            g_ovf_n = 0;
            g_done  = 0;
        }
    }
}

extern "C" void kernel_launch(void* const* d_in, const int* in_sizes, int n_in,
                              void* d_out, int out_size) {
    const float4* x4   = (const float4*)d_in[0];
    const int*    src  = (const int*)d_in[1];
    const int*    dst  = (const int*)d_in[2];
    const float*  attr = (const float*)d_in[3];
    float4*       out4 = (float4*)d_out;

    int E = in_sizes[1];
    int n = out_size / 128;                  // fine nodes (C=128)

    int tb = 256;
    k_bin  <<<(E + tb - 1) / tb, tb>>>(src, dst, attr, E);

    long long gt = (long long)n * 32;
    k_gather<<<(int)((gt + tb - 1) / tb), tb>>>(x4, out4, n);

    k_spill<<<SPILL_BLOCKS, tb>>>(x4, (float*)d_out, SPILL_BLOCKS * 8);
}

// round 14
// speedup vs baseline: 3.2668x; 3.2668x over previous
#include <cuda_runtime.h>
#include <cstdint>

// Graph unpooling: out[dst] += edge_attr * x[src]
//   x [50000,128] f32, src/dst [E=800000] i32, edge_attr [E] f32, out [200000,128] f32
// Fixed-capacity binning: 8 slots per fine node (covers ~98% of Poisson(4)
// fan-in), overflow to a list. reset -> bin -> gather(slots) -> spill(red.add).

#define MAXN   200704
#define MAXE   800000
#define CAP    8
#define SPILL_BLOCKS 296

__device__ int  g_count[MAXN];         // per-node edge count (may exceed CAP)
__device__ int2 g_slots[MAXN * CAP];   // {src, bitcast(weight)} per slot
__device__ int  g_ovf_n;               // overflow counter
__device__ int4 g_ovf[MAXE];           // overflow: {src, dst, w_bits, pad}

__global__ void k_reset(int n) {
    int i = blockIdx.x * blockDim.x + threadIdx.x;
    if (i < n) g_count[i] = 0;
    if (i == 0) g_ovf_n = 0;
}

// Fused hist+fill: bin each edge into its node's slot array (or overflow).
__global__ void k_bin(const int* __restrict__ src, const int* __restrict__ dst,
                      const float* __restrict__ attr, int E) {
    int e = blockIdx.x * blockDim.x + threadIdx.x;
    if (e >= E) return;
    int d = __ldg(&dst[e]);
    int s = __ldg(&src[e]);
    int w = __float_as_int(__ldg(&attr[e]));
    int r = atomicAdd(&g_count[d], 1);
    if (r < CAP) {
        g_slots[d * CAP + r] = make_int2(s, w);
    } else {
        int p = atomicAdd(&g_ovf_n, 1);
        g_ovf[p] = make_int4(s, d, w, 0);
    }
}

// One warp per fine node: predicated 4-burst x2 over the 8 fixed slots,
// register accumulate, single streaming store (keeps x resident in L2).
__global__ void __launch_bounds__(256)
k_gather(const float4* __restrict__ x4, float4* __restrict__ out4, int n) {
    int gtid = blockIdx.x * blockDim.x + threadIdx.x;
    int node = gtid >> 5;
    int lane = gtid & 31;
    if (node >= n) return;

    int cnt = __ldg(&g_count[node]);
    if (cnt > CAP) cnt = CAP;
    int beg = node * CAP;

    const float4 fz = make_float4(0.f, 0.f, 0.f, 0.f);
    float4 a0 = fz, a1 = fz;

    // burst 1: slots 0..3 (covers 63% of nodes entirely)
    int2 e0 = make_int2(0, 0), e1 = e0, e2 = e0, e3 = e0;
    if (cnt > 0) e0 = __ldg(&g_slots[beg]);
    if (cnt > 1) e1 = __ldg(&g_slots[beg + 1]);
    if (cnt > 2) e2 = __ldg(&g_slots[beg + 2]);
    if (cnt > 3) e3 = __ldg(&g_slots[beg + 3]);
    float4 v0 = fz, v1 = fz, v2 = fz, v3 = fz;
    if (cnt > 0) v0 = __ldg(&x4[(size_t)e0.x * 32 + lane]);
    if (cnt > 1) v1 = __ldg(&x4[(size_t)e1.x * 32 + lane]);
    if (cnt > 2) v2 = __ldg(&x4[(size_t)e2.x * 32 + lane]);
    if (cnt > 3) v3 = __ldg(&x4[(size_t)e3.x * 32 + lane]);
    {
        float w0 = __int_as_float(e0.y), w1 = __int_as_float(e1.y);
        float w2 = __int_as_float(e2.y), w3 = __int_as_float(e3.y);
        a0.x += w0 * v0.x; a0.y += w0 * v0.y; a0.z += w0 * v0.z; a0.w += w0 * v0.w;
        a1.x += w1 * v1.x; a1.y += w1 * v1.y; a1.z += w1 * v1.z; a1.w += w1 * v1.w;
        a0.x += w2 * v2.x; a0.y += w2 * v2.y; a0.z += w2 * v2.z; a0.w += w2 * v2.w;
        a1.x += w3 * v3.x; a1.y += w3 * v3.y; a1.z += w3 * v3.z; a1.w += w3 * v3.w;
    }

    // burst 2: slots 4..7 (predicated; rare)
    if (cnt > 4) {
        int2 f0 = __ldg(&g_slots[beg + 4]);
        int2 f1 = make_int2(0, 0), f2 = f1, f3 = f1;
        if (cnt > 5) f1 = __ldg(&g_slots[beg + 5]);
        if (cnt > 6) f2 = __ldg(&g_slots[beg + 6]);
        if (cnt > 7) f3 = __ldg(&g_slots[beg + 7]);
        float4 u0 = __ldg(&x4[(size_t)f0.x * 32 + lane]);
        float4 u1 = fz, u2 = fz, u3 = fz;
        if (cnt > 5) u1 = __ldg(&x4[(size_t)f1.x * 32 + lane]);
        if (cnt > 6) u2 = __ldg(&x4[(size_t)f2.x * 32 + lane]);
        if (cnt > 7) u3 = __ldg(&x4[(size_t)f3.x * 32 + lane]);
        float w0 = __int_as_float(f0.y), w1 = __int_as_float(f1.y);
        float w2 = __int_as_float(f2.y), w3 = __int_as_float(f3.y);
        a0.x += w0 * u0.x; a0.y += w0 * u0.y; a0.z += w0 * u0.z; a0.w += w0 * u0.w;
        a1.x += w1 * u1.x; a1.y += w1 * u1.y; a1.z += w1 * u1.z; a1.w += w1 * u1.w;
        a0.x += w2 * u2.x; a0.y += w2 * u2.y; a0.z += w2 * u2.z; a0.w += w2 * u2.w;
        a1.x += w3 * u3.x; a1.y += w3 * u3.y; a1.z += w3 * u3.z; a1.w += w3 * u3.w;
    }

    a0.x += a1.x; a0.y += a1.y; a0.z += a1.z; a0.w += a1.w;
    __stcs(&out4[(size_t)node * 32 + lane], a0);
}

// Overflow edges: warp per entry, red.add.v4 into out (runs after gather).
// Fixed grid; warps stride over the dynamic overflow count.
__global__ void __launch_bounds__(256)
k_spill(const float4* __restrict__ x4, float* __restrict__ out, int total_warps) {
    int gtid = blockIdx.x * blockDim.x + threadIdx.x;
    int warp = gtid >> 5;
    int lane = gtid & 31;
    int m = g_ovf_n;
    for (int i = warp; i < m; i += total_warps) {
        int4 e = g_ovf[i];
        float w = __int_as_float(e.z);
        float4 v = __ldg(&x4[(size_t)e.x * 32 + lane]);
        v.x *= w; v.y *= w; v.z *= w; v.w *= w;
        float* p = out + (size_t)e.y * 128 + (lane << 2);
        asm volatile("red.global.add.v4.f32 [%0], {%1, %2, %3, %4};"
                     :: "l"(p), "f"(v.x), "f"(v.y), "f"(v.z), "f"(v.w)
                     : "memory");
    }
}

extern "C" void kernel_launch(void* const* d_in, const int* in_sizes, int n_in,
                              void* d_out, int out_size) {
    const float4* x4   = (const float4*)d_in[0];
    const int*    src  = (const int*)d_in[1];
    const int*    dst  = (const int*)d_in[2];
    const float*  attr = (const float*)d_in[3];
    float4*       out4 = (float4*)d_out;

    int E = in_sizes[1];
    int n = out_size / 128;                  // fine nodes (C=128)

    int tb = 256;
    k_reset<<<(n + tb - 1) / tb, tb>>>(n);
    k_bin  <<<(E + tb - 1) / tb, tb>>>(src, dst, attr, E);

    long long gt = (long long)n * 32;
    k_gather<<<(int)((gt + tb - 1) / tb), tb>>>(x4, out4, n);

    k_spill<<<SPILL_BLOCKS, tb>>>(x4, (float*)d_out, SPILL_BLOCKS * 8);
}